// round 7
// baseline (speedup 1.0000x reference)
#include <cuda_runtime.h>
#include <cuda_bf16.h>
#include <cstddef>

#define NN 100000           // nodes
#define D1 128              // input / layer-2 output dim
#define D2 256              // hidden dim

// -------- scratch (no allocation allowed; __device__ globals) --------
__device__ int   g_deg[NN];
__device__ float g_dinv[NN];
__device__ float g_bufA[(size_t)NN * D1];   // agg1, later h2
__device__ float g_bufB[(size_t)NN * D2];   // out1 (post relu)

// ---------------------------------------------------------------
// degree / normalization
// ---------------------------------------------------------------
__global__ void k_deg_init() {
    int i = blockIdx.x * blockDim.x + threadIdx.x;
    if (i < NN) g_deg[i] = 1;   // self loop
}

__global__ void k_deg_count(const int* __restrict__ dst, int E) {
    int i = blockIdx.x * blockDim.x + threadIdx.x;
    if (i >= E) return;
    int d = dst[i];
    if ((unsigned)d < NN) atomicAdd(&g_deg[d], 1);
}

__global__ void k_dinv() {
    int i = blockIdx.x * blockDim.x + threadIdx.x;
    if (i < NN) g_dinv[i] = rsqrtf((float)g_deg[i]);
}

// ---------------------------------------------------------------
// self-loop init: out[n,:] = dinv[n]^2 * src[n,:]   (D1 = 128 dims)
// one thread per float4; 32 float4 per row
// ---------------------------------------------------------------
__global__ void k_self_init(const float* __restrict__ src, float* __restrict__ out) {
    int i = blockIdx.x * blockDim.x + threadIdx.x;
    const int total4 = NN * (D1 / 4);
    if (i >= total4) return;
    int n = i >> 5;                       // / 32
    float w = g_dinv[n]; w *= w;
    float4 v = ((const float4*)src)[i];
    v.x *= w; v.y *= w; v.z *= w; v.w *= w;
    ((float4*)out)[i] = v;
}

// ---------------------------------------------------------------
// edge scatter: out[dst,:] += dinv[s]*dinv[d] * feat[src,:]
// one warp per edge, lane handles 4 floats (128 dims = 32 lanes * float4)
// vectorized gather (LDG.128) + 4 scalar RED.ADD.F32 per lane
// ---------------------------------------------------------------
__global__ void k_scatter(const int* __restrict__ srcIdx,
                          const int* __restrict__ dstIdx,
                          const float* __restrict__ feat,
                          float* __restrict__ out, int E) {
    int e    = (blockIdx.x * blockDim.x + threadIdx.x) >> 5;
    int lane = threadIdx.x & 31;
    if (e >= E) return;
    int s = srcIdx[e];
    int d = dstIdx[e];
    if ((unsigned)s >= NN || (unsigned)d >= NN) return;
    float w = g_dinv[s] * g_dinv[d];
    float4 v = ((const float4*)(feat + (size_t)s * D1))[lane];
    float* base = out + (size_t)d * D1 + lane * 4;
    atomicAdd(base + 0, v.x * w);
    atomicAdd(base + 1, v.y * w);
    atomicAdd(base + 2, v.z * w);
    atomicAdd(base + 3, v.w * w);
}

// ---------------------------------------------------------------
// SGEMM: C[M,N] = A[M,K] * B[K,N] (+bias) (+relu)
// BM=BN=64, BK=16, 256 threads, 4x4 microtile per thread
// ---------------------------------------------------------------
template<bool RELU, bool BIAS>
__global__ __launch_bounds__(256)
void gemm_kernel(const float* __restrict__ A, const float* __restrict__ B,
                 const float* __restrict__ bias, float* __restrict__ C,
                 int M, int N, int K)
{
    constexpr int BM = 64, BN = 64, BK = 16;
    __shared__ float As[BK][BM];   // transposed A tile
    __shared__ float Bs[BK][BN];

    const int tid = threadIdx.x;
    const int tx  = tid & 15;      // 0..15  -> 4 cols each
    const int ty  = tid >> 4;      // 0..15  -> 4 rows each
    const int bm  = blockIdx.y * BM;
    const int bn  = blockIdx.x * BN;

    // A-tile load mapping: 64x16 = 1024 floats / 256 thr = 1 float4 each
    const int ar = tid >> 2;          // row in tile 0..63
    const int ac = (tid & 3) * 4;     // k-col 0,4,8,12
    // B-tile load mapping: 16x64 floats
    const int br = tid >> 4;          // k-row 0..15
    const int bc = (tid & 15) * 4;    // col 0..60

    float acc[4][4] = {};

    for (int k0 = 0; k0 < K; k0 += BK) {
        float4 av = make_float4(0.f, 0.f, 0.f, 0.f);
        int am = bm + ar;
        if (am < M) av = *(const float4*)(A + (size_t)am * K + k0 + ac);
        As[ac + 0][ar] = av.x;
        As[ac + 1][ar] = av.y;
        As[ac + 2][ar] = av.z;
        As[ac + 3][ar] = av.w;

        float4 bv = *(const float4*)(B + (size_t)(k0 + br) * N + bn + bc);
        *(float4*)&Bs[br][bc] = bv;

        __syncthreads();

        #pragma unroll
        for (int kk = 0; kk < BK; kk++) {
            float4 a = *(const float4*)&As[kk][ty * 4];
            float4 b = *(const float4*)&Bs[kk][tx * 4];
            acc[0][0] += a.x * b.x; acc[0][1] += a.x * b.y; acc[0][2] += a.x * b.z; acc[0][3] += a.x * b.w;
            acc[1][0] += a.y * b.x; acc[1][1] += a.y * b.y; acc[1][2] += a.y * b.z; acc[1][3] += a.y * b.w;
            acc[2][0] += a.z * b.x; acc[2][1] += a.z * b.y; acc[2][2] += a.z * b.z; acc[2][3] += a.z * b.w;
            acc[3][0] += a.w * b.x; acc[3][1] += a.w * b.y; acc[3][2] += a.w * b.z; acc[3][3] += a.w * b.w;
        }
        __syncthreads();
    }

    float4 bb = make_float4(0.f, 0.f, 0.f, 0.f);
    if (BIAS) bb = *(const float4*)(bias + bn + tx * 4);

    #pragma unroll
    for (int i = 0; i < 4; i++) {
        int m = bm + ty * 4 + i;
        if (m >= M) continue;
        float4 v;
        v.x = acc[i][0] + bb.x;
        v.y = acc[i][1] + bb.y;
        v.z = acc[i][2] + bb.z;
        v.w = acc[i][3] + bb.w;
        if (RELU) {
            v.x = fmaxf(v.x, 0.f); v.y = fmaxf(v.y, 0.f);
            v.z = fmaxf(v.z, 0.f); v.w = fmaxf(v.w, 0.f);
        }
        *(float4*)(C + (size_t)m * N + bn + tx * 4) = v;
    }
}

// ---------------------------------------------------------------
// final: out = relu(out + b2)   (128 dims)
// ---------------------------------------------------------------
__global__ void k_finish(float* __restrict__ out, const float* __restrict__ bias) {
    int i = blockIdx.x * blockDim.x + threadIdx.x;
    const int total4 = NN * (D1 / 4);
    if (i >= total4) return;
    int c4 = (i & 31) * 4;
    float4 b = *(const float4*)(bias + c4);
    float4 v = ((float4*)out)[i];
    v.x = fmaxf(v.x + b.x, 0.f);
    v.y = fmaxf(v.y + b.y, 0.f);
    v.z = fmaxf(v.z + b.z, 0.f);
    v.w = fmaxf(v.w + b.w, 0.f);
    ((float4*)out)[i] = v;
}

// ---------------------------------------------------------------
// launch
// ---------------------------------------------------------------
extern "C" void kernel_launch(void* const* d_in, const int* in_sizes, int n_in,
                              void* d_out, int out_size)
{
    const float* x   = (const float*)d_in[0];
    const int*   ei  = (const int*)d_in[1];      // int32 (JAX x64 disabled)
    const float* W1  = (const float*)d_in[2];
    const float* b1  = (const float*)d_in[3];
    const float* W2  = (const float*)d_in[4];
    const float* b2  = (const float*)d_in[5];
    float*       out = (float*)d_out;

    const int E = in_sizes[1] / 2;
    const int* srcIdx = ei;
    const int* dstIdx = ei + E;

    float* bufA = nullptr;  cudaGetSymbolAddress((void**)&bufA, g_bufA);
    float* bufB = nullptr;  cudaGetSymbolAddress((void**)&bufB, g_bufB);

    const int T = 256;

    // 1) degree + dinv
    k_deg_init<<<(NN + T - 1) / T, T>>>();
    k_deg_count<<<(E + T - 1) / T, T>>>(dstIdx, E);
    k_dinv<<<(NN + T - 1) / T, T>>>();

    // 2) layer-1 aggregation in 128-dim input space: bufA = A_norm @ x
    const int total4 = NN * (D1 / 4);
    k_self_init<<<(total4 + T - 1) / T, T>>>(x, bufA);
    k_scatter<<<(E * 32 + T - 1) / T, T>>>(srcIdx, dstIdx, x, bufA, E);

    // 3) out1 = relu(bufA @ W1 + b1)  -> bufB [N, 256]
    {
        dim3 grid(D2 / 64, (NN + 63) / 64);
        gemm_kernel<true, true><<<grid, 256>>>(bufA, W1, b1, bufB, NN, D2, D1);
    }

    // 4) h2 = bufB @ W2 -> bufA [N, 128]
    {
        dim3 grid(D1 / 64, (NN + 63) / 64);
        gemm_kernel<false, false><<<grid, 256>>>(bufB, W2, nullptr, bufA, NN, D1, D2);
    }

    // 5) layer-2 aggregation into d_out, then bias+relu
    k_self_init<<<(total4 + T - 1) / T, T>>>(bufA, out);
    k_scatter<<<(E * 32 + T - 1) / T, T>>>(srcIdx, dstIdx, bufA, out, E);
    k_finish<<<(total4 + T - 1) / T, T>>>(out, b2);
}

// round 8
// speedup vs baseline: 1.6718x; 1.6718x over previous
#include <cuda_runtime.h>
#include <cuda_bf16.h>
#include <cstddef>

#define NN    100000        // nodes
#define D1    128           // input / layer-2 output dim
#define D2    256           // hidden dim
#define EMAX  700000        // max edges (setup uses 600k)
#define NCHUNK ((NN + 1023) / 1024)

// -------- scratch (no allocation allowed; __device__ globals) --------
__device__ int   g_cnt[NN];             // in-edge counts (no self loop)
__device__ float g_dinv[NN];
__device__ int   g_off[NN + 1];         // CSR row offsets
__device__ int   g_cursor[NN];          // placement cursors
__device__ int   g_csum[NCHUNK];        // chunk sums for scan
__device__ int   g_csr[EMAX];           // CSR column (src) indices
__device__ float g_bufA[(size_t)NN * D1];   // agg1, later h2
__device__ float g_bufB[(size_t)NN * D2];   // out1 (post relu)

// ---------------------------------------------------------------
// degree count + normalization
// ---------------------------------------------------------------
__global__ void k_zero_cnt() {
    int i = blockIdx.x * blockDim.x + threadIdx.x;
    if (i < NN) g_cnt[i] = 0;
}

__global__ void k_deg_count(const int* __restrict__ dst, int E) {
    int i = blockIdx.x * blockDim.x + threadIdx.x;
    if (i >= E) return;
    int d = dst[i];
    if ((unsigned)d < NN) atomicAdd(&g_cnt[d], 1);
}

__global__ void k_dinv() {
    int i = blockIdx.x * blockDim.x + threadIdx.x;
    if (i < NN) g_dinv[i] = rsqrtf((float)(g_cnt[i] + 1));   // +1 self loop
}

// ---------------------------------------------------------------
// exclusive scan of g_cnt -> g_off  (3-phase block scan)
// ---------------------------------------------------------------
__global__ __launch_bounds__(1024) void k_scan1() {
    __shared__ int sh[1024];
    int t   = threadIdx.x;
    int idx = blockIdx.x * 1024 + t;
    int v   = (idx < NN) ? g_cnt[idx] : 0;
    sh[t] = v;
    __syncthreads();
    #pragma unroll
    for (int off = 1; off < 1024; off <<= 1) {
        int add = (t >= off) ? sh[t - off] : 0;
        __syncthreads();
        sh[t] += add;
        __syncthreads();
    }
    if (idx < NN) g_off[idx] = sh[t] - v;          // exclusive within chunk
    if (t == 1023) g_csum[blockIdx.x] = sh[1023];  // chunk total
}

__global__ void k_scan2() {
    if (threadIdx.x == 0) {
        int run = 0;
        for (int i = 0; i < NCHUNK; i++) { int c = g_csum[i]; g_csum[i] = run; run += c; }
        g_off[NN] = run;                           // total valid edges
    }
}

__global__ void k_scan3() {
    int i = blockIdx.x * blockDim.x + threadIdx.x;
    if (i < NN) {
        g_off[i] += g_csum[i >> 10];
        g_cursor[i] = 0;
    }
}

// ---------------------------------------------------------------
// CSR placement: bucket edges by dst
// ---------------------------------------------------------------
__global__ void k_place(const int* __restrict__ srcIdx,
                        const int* __restrict__ dstIdx, int E) {
    int e = blockIdx.x * blockDim.x + threadIdx.x;
    if (e >= E) return;
    int s = srcIdx[e], d = dstIdx[e];
    if ((unsigned)s >= NN || (unsigned)d >= NN) return;
    int pos = g_off[d] + atomicAdd(&g_cursor[d], 1);
    g_csr[pos] = s;
}

// ---------------------------------------------------------------
// CSR gather: out[n,:] = dinv[n]^2*feat[n,:] + sum_e dinv[n]dinv[s]*feat[s,:]
// one warp per node; lane owns 4 dims (float4). optional bias+relu on write.
// ---------------------------------------------------------------
template<bool RELU, bool BIAS>
__global__ __launch_bounds__(256)
void k_gather(const float* __restrict__ feat, float* __restrict__ out,
              const float* __restrict__ bias) {
    int gtid = blockIdx.x * blockDim.x + threadIdx.x;
    int n    = gtid >> 5;
    int lane = gtid & 31;
    if (n >= NN) return;

    float dn = g_dinv[n];
    float4 acc = ((const float4*)(feat + (size_t)n * D1))[lane];
    float w0 = dn * dn;
    acc.x *= w0; acc.y *= w0; acc.z *= w0; acc.w *= w0;

    int e   = g_off[n];
    int end = g_off[n + 1];
    int s_next = (e < end) ? g_csr[e] : 0;
    for (; e < end; e++) {
        int s = s_next;
        if (e + 1 < end) s_next = g_csr[e + 1];
        float w = dn * g_dinv[s];
        float4 v = ((const float4*)(feat + (size_t)s * D1))[lane];
        acc.x += w * v.x; acc.y += w * v.y; acc.z += w * v.z; acc.w += w * v.w;
    }

    if (BIAS) {
        float4 b = *(const float4*)(bias + lane * 4);
        acc.x += b.x; acc.y += b.y; acc.z += b.z; acc.w += b.w;
    }
    if (RELU) {
        acc.x = fmaxf(acc.x, 0.f); acc.y = fmaxf(acc.y, 0.f);
        acc.z = fmaxf(acc.z, 0.f); acc.w = fmaxf(acc.w, 0.f);
    }
    ((float4*)(out + (size_t)n * D1))[lane] = acc;
}

// ---------------------------------------------------------------
// SGEMM: C[M,N] = A[M,K] * B[K,N] (+bias)(+relu)
// BM=BN=128, BK=8, 256 threads, 8x8 microtile
// ---------------------------------------------------------------
template<bool RELU, bool BIAS>
__global__ __launch_bounds__(256)
void gemm_kernel(const float* __restrict__ A, const float* __restrict__ B,
                 const float* __restrict__ bias, float* __restrict__ C,
                 int M, int N, int K)
{
    constexpr int BM = 128, BN = 128, BK = 8;
    __shared__ float As[BK][BM];
    __shared__ float Bs[BK][BN];

    const int tid = threadIdx.x;
    const int tx  = tid & 15;          // col group (8 cols each)
    const int ty  = tid >> 4;          // row group (8 rows each)
    const int bm  = blockIdx.y * BM;
    const int bn  = blockIdx.x * BN;

    // A tile: 128 rows x 8 k -> each thread one float4: row=tid>>1, k=(tid&1)*4
    const int ar = tid >> 1;
    const int ac = (tid & 1) * 4;
    // B tile: 8 k x 128 cols -> row=tid>>5, col=(tid&31)*4
    const int br = tid >> 5;
    const int bc = (tid & 31) * 4;

    float acc[8][8] = {};
    float a_reg[8], b_reg[8];

    for (int k0 = 0; k0 < K; k0 += BK) {
        float4 av = make_float4(0.f, 0.f, 0.f, 0.f);
        int am = bm + ar;
        if (am < M) av = *(const float4*)(A + (size_t)am * K + k0 + ac);
        As[ac + 0][ar] = av.x;
        As[ac + 1][ar] = av.y;
        As[ac + 2][ar] = av.z;
        As[ac + 3][ar] = av.w;

        float4 bv = *(const float4*)(B + (size_t)(k0 + br) * N + bn + bc);
        *(float4*)&Bs[br][bc] = bv;

        __syncthreads();

        #pragma unroll
        for (int kk = 0; kk < BK; kk++) {
            *(float4*)&a_reg[0] = *(const float4*)&As[kk][ty * 8];
            *(float4*)&a_reg[4] = *(const float4*)&As[kk][ty * 8 + 4];
            *(float4*)&b_reg[0] = *(const float4*)&Bs[kk][tx * 8];
            *(float4*)&b_reg[4] = *(const float4*)&Bs[kk][tx * 8 + 4];
            #pragma unroll
            for (int i = 0; i < 8; i++)
                #pragma unroll
                for (int j = 0; j < 8; j++)
                    acc[i][j] += a_reg[i] * b_reg[j];
        }
        __syncthreads();
    }

    float bb[8];
    if (BIAS) {
        *(float4*)&bb[0] = *(const float4*)(bias + bn + tx * 8);
        *(float4*)&bb[4] = *(const float4*)(bias + bn + tx * 8 + 4);
    }

    #pragma unroll
    for (int i = 0; i < 8; i++) {
        int m = bm + ty * 8 + i;
        if (m >= M) continue;
        float r[8];
        #pragma unroll
        for (int j = 0; j < 8; j++) {
            float v = acc[i][j];
            if (BIAS) v += bb[j];
            if (RELU) v = fmaxf(v, 0.f);
            r[j] = v;
        }
        *(float4*)(C + (size_t)m * N + bn + tx * 8)     = *(float4*)&r[0];
        *(float4*)(C + (size_t)m * N + bn + tx * 8 + 4) = *(float4*)&r[4];
    }
}

// ---------------------------------------------------------------
// launch
// ---------------------------------------------------------------
extern "C" void kernel_launch(void* const* d_in, const int* in_sizes, int n_in,
                              void* d_out, int out_size)
{
    const float* x   = (const float*)d_in[0];
    const int*   ei  = (const int*)d_in[1];      // int32 (JAX x64 disabled)
    const float* W1  = (const float*)d_in[2];
    const float* b1  = (const float*)d_in[3];
    const float* W2  = (const float*)d_in[4];
    const float* b2  = (const float*)d_in[5];
    float*       out = (float*)d_out;

    const int E = in_sizes[1] / 2;
    const int* srcIdx = ei;
    const int* dstIdx = ei + E;

    float* bufA = nullptr;  cudaGetSymbolAddress((void**)&bufA, g_bufA);
    float* bufB = nullptr;  cudaGetSymbolAddress((void**)&bufB, g_bufB);

    const int T = 256;

    // 1) degree + dinv + CSR build
    k_zero_cnt<<<(NN + T - 1) / T, T>>>();
    k_deg_count<<<(E + T - 1) / T, T>>>(dstIdx, E);
    k_dinv<<<(NN + T - 1) / T, T>>>();
    k_scan1<<<NCHUNK, 1024>>>();
    k_scan2<<<1, 32>>>();
    k_scan3<<<(NN + T - 1) / T, T>>>();
    k_place<<<(E + T - 1) / T, T>>>(srcIdx, dstIdx, E);

    // 2) layer-1 aggregation (gather): bufA = A_norm @ x
    const int gthreads = NN * 32;
    k_gather<false, false><<<(gthreads + T - 1) / T, T>>>(x, bufA, nullptr);

    // 3) out1 = relu(bufA @ W1 + b1) -> bufB [N, 256]
    {
        dim3 grid(D2 / 128, (NN + 127) / 128);
        gemm_kernel<true, true><<<grid, 256>>>(bufA, W1, b1, bufB, NN, D2, D1);
    }

    // 4) h2 = bufB @ W2 -> bufA [N, 128]
    {
        dim3 grid(D1 / 128, (NN + 127) / 128);
        gemm_kernel<false, false><<<grid, 256>>>(bufB, W2, nullptr, bufA, NN, D1, D2);
    }

    // 5) layer-2 aggregation (gather) + bias + relu -> out
    k_gather<true, true><<<(gthreads + T - 1) / T, T>>>(bufA, out, b2);
}

// round 9
// speedup vs baseline: 3.1839x; 1.9045x over previous
#include <cuda_runtime.h>
#include <cuda_bf16.h>
#include <cstddef>

#define NN    100000        // nodes
#define D1    128           // input / layer-2 output dim
#define D2    256           // hidden dim
#define EMAX  700000        // max edges (setup uses 600k)
#define NCHUNK ((NN + 1023) / 1024)

// -------- scratch (no allocation allowed; __device__ globals) --------
__device__ int   g_cnt[NN];             // in-edge counts (no self loop)
__device__ float g_dinv[NN];
__device__ int   g_off[NN + 1];         // CSR row offsets
__device__ int   g_cursor[NN];          // placement cursors
__device__ int   g_csum[NCHUNK];        // chunk sums for scan
__device__ int   g_csr[EMAX];           // CSR column (src) indices
__device__ float g_bufA[(size_t)NN * D1];   // agg1, later h2
__device__ float g_bufB[(size_t)NN * D2];   // out1 (post relu)

// ---------------------------------------------------------------
// degree count + normalization
// ---------------------------------------------------------------
__global__ void k_zero_cnt() {
    int i = blockIdx.x * blockDim.x + threadIdx.x;
    if (i < NN) g_cnt[i] = 0;
}

__global__ void k_deg_count(const int* __restrict__ dst, int E) {
    int i = blockIdx.x * blockDim.x + threadIdx.x;
    if (i >= E) return;
    int d = dst[i];
    if ((unsigned)d < NN) atomicAdd(&g_cnt[d], 1);
}

__global__ void k_dinv() {
    int i = blockIdx.x * blockDim.x + threadIdx.x;
    if (i < NN) g_dinv[i] = rsqrtf((float)(g_cnt[i] + 1));   // +1 self loop
}

// ---------------------------------------------------------------
// exclusive scan of g_cnt -> g_off  (3-phase block scan)
// ---------------------------------------------------------------
__global__ __launch_bounds__(1024) void k_scan1() {
    __shared__ int sh[1024];
    int t   = threadIdx.x;
    int idx = blockIdx.x * 1024 + t;
    int v   = (idx < NN) ? g_cnt[idx] : 0;
    sh[t] = v;
    __syncthreads();
    #pragma unroll
    for (int off = 1; off < 1024; off <<= 1) {
        int add = (t >= off) ? sh[t - off] : 0;
        __syncthreads();
        sh[t] += add;
        __syncthreads();
    }
    if (idx < NN) g_off[idx] = sh[t] - v;          // exclusive within chunk
    if (t == 1023) g_csum[blockIdx.x] = sh[1023];  // chunk total
}

__global__ void k_scan2() {
    if (threadIdx.x == 0) {
        int run = 0;
        for (int i = 0; i < NCHUNK; i++) { int c = g_csum[i]; g_csum[i] = run; run += c; }
        g_off[NN] = run;                           // total valid edges
    }
}

__global__ void k_scan3() {
    int i = blockIdx.x * blockDim.x + threadIdx.x;
    if (i < NN) {
        g_off[i] += g_csum[i >> 10];
        g_cursor[i] = 0;
    }
}

// ---------------------------------------------------------------
// CSR placement: bucket edges by dst
// ---------------------------------------------------------------
__global__ void k_place(const int* __restrict__ srcIdx,
                        const int* __restrict__ dstIdx, int E) {
    int e = blockIdx.x * blockDim.x + threadIdx.x;
    if (e >= E) return;
    int s = srcIdx[e], d = dstIdx[e];
    if ((unsigned)s >= NN || (unsigned)d >= NN) return;
    int pos = g_off[d] + atomicAdd(&g_cursor[d], 1);
    g_csr[pos] = s;
}

// ---------------------------------------------------------------
// CSR gather: out[n,:] = dinv[n]^2*feat[n,:] + sum_e dinv[n]dinv[s]*feat[s,:]
// one warp per node; lane owns 4 dims (float4). optional bias+relu on write.
// ---------------------------------------------------------------
template<bool RELU, bool BIAS>
__global__ __launch_bounds__(256)
void k_gather(const float* __restrict__ feat, float* __restrict__ out,
              const float* __restrict__ bias) {
    int gtid = blockIdx.x * blockDim.x + threadIdx.x;
    int n    = gtid >> 5;
    int lane = gtid & 31;
    if (n >= NN) return;

    float dn = g_dinv[n];
    float4 acc = ((const float4*)(feat + (size_t)n * D1))[lane];
    float w0 = dn * dn;
    acc.x *= w0; acc.y *= w0; acc.z *= w0; acc.w *= w0;

    int e   = g_off[n];
    int end = g_off[n + 1];
    int s_next = (e < end) ? g_csr[e] : 0;
    for (; e < end; e++) {
        int s = s_next;
        if (e + 1 < end) s_next = g_csr[e + 1];
        float w = dn * g_dinv[s];
        float4 v = ((const float4*)(feat + (size_t)s * D1))[lane];
        acc.x += w * v.x; acc.y += w * v.y; acc.z += w * v.z; acc.w += w * v.w;
    }

    if (BIAS) {
        float4 b = *(const float4*)(bias + lane * 4);
        acc.x += b.x; acc.y += b.y; acc.z += b.z; acc.w += b.w;
    }
    if (RELU) {
        acc.x = fmaxf(acc.x, 0.f); acc.y = fmaxf(acc.y, 0.f);
        acc.z = fmaxf(acc.z, 0.f); acc.w = fmaxf(acc.w, 0.f);
    }
    ((float4*)(out + (size_t)n * D1))[lane] = acc;
}

// ---------------------------------------------------------------
// TF32 tensor-core GEMM: C[M,N] = A[M,K] * B[K,N] (+bias)(+relu)
// CTA tile 128x128, BK=32, 256 threads (8 warps), warp tile 32x64.
// mma.sync.aligned.m16n8k8.row.col.f32.tf32.tf32.f32
// fp32->tf32 conversion on the smem store path (cvt.rna).
// ---------------------------------------------------------------
__device__ __forceinline__ float f2tf32(float x) {
    unsigned u;
    asm("cvt.rna.tf32.f32 %0, %1;" : "=r"(u) : "f"(x));
    return __uint_as_float(u);
}

__device__ __forceinline__ void mma_tf32(float* d, const unsigned* a, const unsigned* b) {
    asm volatile(
        "mma.sync.aligned.m16n8k8.row.col.f32.tf32.tf32.f32 "
        "{%0,%1,%2,%3}, {%4,%5,%6,%7}, {%8,%9}, {%0,%1,%2,%3};"
        : "+f"(d[0]), "+f"(d[1]), "+f"(d[2]), "+f"(d[3])
        : "r"(a[0]), "r"(a[1]), "r"(a[2]), "r"(a[3]), "r"(b[0]), "r"(b[1]));
}

template<bool RELU, bool BIAS>
__global__ __launch_bounds__(256)
void gemm_tf32(const float* __restrict__ A, const float* __restrict__ B,
               const float* __restrict__ bias, float* __restrict__ C,
               int M, int N, int K)
{
    constexpr int BM = 128, BN = 128, BK = 32;
    constexpr int APAD = 36;   // 128x36 floats (pad kills stride-32 conflicts)
    constexpr int BPAD = 132;  // 32x132 floats
    __shared__ float As[BM][APAD];
    __shared__ float Bs[BK][BPAD];

    const int tid  = threadIdx.x;
    const int lane = tid & 31;
    const int wid  = tid >> 5;
    const int wr   = wid >> 1;     // warp row 0..3 (32 M-rows each)
    const int wc   = wid & 1;      // warp col 0..1 (64 N-cols each)
    const int bm   = blockIdx.y * BM;
    const int bn   = blockIdx.x * BN;

    float acc[2][8][4];
    #pragma unroll
    for (int i = 0; i < 2; i++)
        #pragma unroll
        for (int j = 0; j < 8; j++)
            #pragma unroll
            for (int q = 0; q < 4; q++) acc[i][j][q] = 0.f;

    for (int k0 = 0; k0 < K; k0 += BK) {
        // load A tile: 4 passes, thread -> row tid/8 (+32/pass), cols (tid%8)*4
        #pragma unroll
        for (int p = 0; p < 4; p++) {
            int r = (tid >> 3) + p * 32;
            int c = (tid & 7) * 4;
            float4 v = make_float4(0.f, 0.f, 0.f, 0.f);
            int am = bm + r;
            if (am < M) v = *(const float4*)(A + (size_t)am * K + k0 + c);
            v.x = f2tf32(v.x); v.y = f2tf32(v.y); v.z = f2tf32(v.z); v.w = f2tf32(v.w);
            *(float4*)&As[r][c] = v;
        }
        // load B tile: 4 passes, row tid/32 (+8/pass), cols (tid%32)*4
        #pragma unroll
        for (int p = 0; p < 4; p++) {
            int r = (tid >> 5) + p * 8;
            int c = (tid & 31) * 4;
            float4 v = *(const float4*)(B + (size_t)(k0 + r) * N + bn + c);
            v.x = f2tf32(v.x); v.y = f2tf32(v.y); v.z = f2tf32(v.z); v.w = f2tf32(v.w);
            *(float4*)&Bs[r][c] = v;
        }
        __syncthreads();

        #pragma unroll
        for (int kk = 0; kk < BK; kk += 8) {
            // A fragments (m16k8): a0 r=g,c=t; a1 r=g+8,c=t; a2 r=g,c=t+4; a3 r=g+8,c=t+4
            unsigned a[2][4];
            int g  = lane >> 2;
            int t4 = lane & 3;
            #pragma unroll
            for (int mt = 0; mt < 2; mt++) {
                int rb = wr * 32 + mt * 16 + g;
                a[mt][0] = __float_as_uint(As[rb    ][kk + t4    ]);
                a[mt][1] = __float_as_uint(As[rb + 8][kk + t4    ]);
                a[mt][2] = __float_as_uint(As[rb    ][kk + t4 + 4]);
                a[mt][3] = __float_as_uint(As[rb + 8][kk + t4 + 4]);
            }
            // B fragments (k8n8): b0 k=t,n=g ; b1 k=t+4,n=g
            unsigned b[8][2];
            #pragma unroll
            for (int nt = 0; nt < 8; nt++) {
                int nb = wc * 64 + nt * 8 + g;
                b[nt][0] = __float_as_uint(Bs[kk + t4    ][nb]);
                b[nt][1] = __float_as_uint(Bs[kk + t4 + 4][nb]);
            }
            #pragma unroll
            for (int mt = 0; mt < 2; mt++)
                #pragma unroll
                for (int nt = 0; nt < 8; nt++)
                    mma_tf32(acc[mt][nt], a[mt], b[nt]);
        }
        __syncthreads();
    }

    // epilogue: c0,c1 -> row g, cols 2t,2t+1 ; c2,c3 -> row g+8
    const int g  = lane >> 2;
    const int t4 = lane & 3;
    #pragma unroll
    for (int mt = 0; mt < 2; mt++) {
        #pragma unroll
        for (int nt = 0; nt < 8; nt++) {
            int col = bn + wc * 64 + nt * 8 + 2 * t4;
            float bx = 0.f, by = 0.f;
            if (BIAS) { bx = bias[col]; by = bias[col + 1]; }
            int r0 = bm + wr * 32 + mt * 16 + g;
            if (r0 < M) {
                float2 v;
                v.x = acc[mt][nt][0] + bx;
                v.y = acc[mt][nt][1] + by;
                if (RELU) { v.x = fmaxf(v.x, 0.f); v.y = fmaxf(v.y, 0.f); }
                *(float2*)(C + (size_t)r0 * N + col) = v;
            }
            int r1 = r0 + 8;
            if (r1 < M) {
                float2 v;
                v.x = acc[mt][nt][2] + bx;
                v.y = acc[mt][nt][3] + by;
                if (RELU) { v.x = fmaxf(v.x, 0.f); v.y = fmaxf(v.y, 0.f); }
                *(float2*)(C + (size_t)r1 * N + col) = v;
            }
        }
    }
}

// ---------------------------------------------------------------
// launch
// ---------------------------------------------------------------
extern "C" void kernel_launch(void* const* d_in, const int* in_sizes, int n_in,
                              void* d_out, int out_size)
{
    const float* x   = (const float*)d_in[0];
    const int*   ei  = (const int*)d_in[1];      // int32 (JAX x64 disabled)
    const float* W1  = (const float*)d_in[2];
    const float* b1  = (const float*)d_in[3];
    const float* W2  = (const float*)d_in[4];
    const float* b2  = (const float*)d_in[5];
    float*       out = (float*)d_out;

    const int E = in_sizes[1] / 2;
    const int* srcIdx = ei;
    const int* dstIdx = ei + E;

    float* bufA = nullptr;  cudaGetSymbolAddress((void**)&bufA, g_bufA);
    float* bufB = nullptr;  cudaGetSymbolAddress((void**)&bufB, g_bufB);

    const int T = 256;

    // 1) degree + dinv + CSR build
    k_zero_cnt<<<(NN + T - 1) / T, T>>>();
    k_deg_count<<<(E + T - 1) / T, T>>>(dstIdx, E);
    k_dinv<<<(NN + T - 1) / T, T>>>();
    k_scan1<<<NCHUNK, 1024>>>();
    k_scan2<<<1, 32>>>();
    k_scan3<<<(NN + T - 1) / T, T>>>();
    k_place<<<(E + T - 1) / T, T>>>(srcIdx, dstIdx, E);

    // 2) layer-1 aggregation (gather): bufA = A_norm @ x
    const int gthreads = NN * 32;
    k_gather<false, false><<<(gthreads + T - 1) / T, T>>>(x, bufA, nullptr);

    // 3) out1 = relu(bufA @ W1 + b1) -> bufB [N, 256]
    {
        dim3 grid(D2 / 128, (NN + 127) / 128);
        gemm_tf32<true, true><<<grid, 256>>>(bufA, W1, b1, bufB, NN, D2, D1);
    }

    // 4) h2 = bufB @ W2 -> bufA [N, 128]
    {
        dim3 grid(D1 / 128, (NN + 127) / 128);
        gemm_tf32<false, false><<<grid, 256>>>(bufB, W2, nullptr, bufA, NN, D1, D2);
    }

    // 5) layer-2 aggregation (gather) + bias + relu -> out
    k_gather<true, true><<<(gthreads + T - 1) / T, T>>>(bufA, out, b2);
}

// round 12
// speedup vs baseline: 3.4011x; 1.0682x over previous
#include <cuda_runtime.h>
#include <cuda_bf16.h>
#include <cstddef>
#include <cstdint>

#define NN    100000        // nodes
#define D1    128           // input / layer-2 output dim
#define D2    256           // hidden dim
#define EMAX  700000        // max edges (setup uses 600k)
#define NCHUNK ((NN + 1023) / 1024)

// -------- scratch (no allocation allowed; __device__ globals) --------
__device__ int   g_cnt[NN];             // in-edge counts (no self loop)
__device__ float g_dinv[NN];
__device__ int   g_off[NN + 1];         // CSR row offsets
__device__ int   g_cursor[NN];          // placement cursors
__device__ int   g_csum[NCHUNK];        // chunk sums for scan
__device__ int   g_csr[EMAX];           // CSR column (src) indices
__device__ float g_bufA[(size_t)NN * D1];   // agg1 (tf32-rounded), later h2 (f32)
__device__ float g_bufB[(size_t)NN * D2];   // out1 (post relu, tf32-rounded)
__device__ float g_W1t[D1 * D2];            // tf32-rounded weights
__device__ float g_W2t[D2 * D1];

__device__ __forceinline__ float f2tf32(float x) {
    unsigned u;
    asm("cvt.rna.tf32.f32 %0, %1;" : "=r"(u) : "f"(x));
    return __uint_as_float(u);
}

__device__ __forceinline__ void cp_async16(uint32_t smem, const void* gmem, int szbytes) {
    asm volatile("cp.async.cg.shared.global [%0], [%1], 16, %2;"
                 :: "r"(smem), "l"(gmem), "r"(szbytes));
}

// ---------------------------------------------------------------
// degree count + normalization
// ---------------------------------------------------------------
__global__ void k_zero_cnt() {
    int i = blockIdx.x * blockDim.x + threadIdx.x;
    if (i < NN) g_cnt[i] = 0;
}

__global__ void k_deg_count(const int* __restrict__ dst, int E) {
    int i = blockIdx.x * blockDim.x + threadIdx.x;
    if (i >= E) return;
    int d = dst[i];
    if ((unsigned)d < NN) atomicAdd(&g_cnt[d], 1);
}

__global__ void k_dinv() {
    int i = blockIdx.x * blockDim.x + threadIdx.x;
    if (i < NN) g_dinv[i] = rsqrtf((float)(g_cnt[i] + 1));   // +1 self loop
}

// weight pre-round to tf32
__global__ void k_cvt(const float* __restrict__ src, float* __restrict__ dst, int n) {
    int i = blockIdx.x * blockDim.x + threadIdx.x;
    if (i < n) dst[i] = f2tf32(src[i]);
}

// ---------------------------------------------------------------
// exclusive scan of g_cnt -> g_off  (3-phase block scan)
// ---------------------------------------------------------------
__global__ __launch_bounds__(1024) void k_scan1() {
    __shared__ int sh[1024];
    int t   = threadIdx.x;
    int idx = blockIdx.x * 1024 + t;
    int v   = (idx < NN) ? g_cnt[idx] : 0;
    sh[t] = v;
    __syncthreads();
    #pragma unroll
    for (int off = 1; off < 1024; off <<= 1) {
        int add = (t >= off) ? sh[t - off] : 0;
        __syncthreads();
        sh[t] += add;
        __syncthreads();
    }
    if (idx < NN) g_off[idx] = sh[t] - v;          // exclusive within chunk
    if (t == 1023) g_csum[blockIdx.x] = sh[1023];  // chunk total
}

__global__ void k_scan2() {
    if (threadIdx.x == 0) {
        int run = 0;
        for (int i = 0; i < NCHUNK; i++) { int c = g_csum[i]; g_csum[i] = run; run += c; }
        g_off[NN] = run;
    }
}

__global__ void k_scan3() {
    int i = blockIdx.x * blockDim.x + threadIdx.x;
    if (i < NN) {
        g_off[i] += g_csum[i >> 10];
        g_cursor[i] = 0;
    }
}

// ---------------------------------------------------------------
// CSR placement: bucket edges by dst
// ---------------------------------------------------------------
__global__ void k_place(const int* __restrict__ srcIdx,
                        const int* __restrict__ dstIdx, int E) {
    int e = blockIdx.x * blockDim.x + threadIdx.x;
    if (e >= E) return;
    int s = srcIdx[e], d = dstIdx[e];
    if ((unsigned)s >= NN || (unsigned)d >= NN) return;
    int pos = g_off[d] + atomicAdd(&g_cursor[d], 1);
    g_csr[pos] = s;
}

// ---------------------------------------------------------------
// CSR gather: out[n,:] = dinv[n]^2*feat[n,:] + sum_e dinv[n]dinv[s]*feat[s,:]
// one warp per node; lane owns 4 dims (float4). 2x unrolled edge loop.
// CVT: round output to tf32 (when it feeds a GEMM A operand).
// ---------------------------------------------------------------
template<bool RELU, bool BIAS, bool CVT>
__global__ __launch_bounds__(256)
void k_gather(const float* __restrict__ feat, float* __restrict__ out,
              const float* __restrict__ bias) {
    int gtid = blockIdx.x * blockDim.x + threadIdx.x;
    int n    = gtid >> 5;
    int lane = gtid & 31;
    if (n >= NN) return;

    float dn = g_dinv[n];
    float4 acc = ((const float4*)(feat + (size_t)n * D1))[lane];
    float w0 = dn * dn;
    acc.x *= w0; acc.y *= w0; acc.z *= w0; acc.w *= w0;

    int e   = g_off[n];
    int end = g_off[n + 1];
    for (; e + 1 < end; e += 2) {
        int s0 = g_csr[e];
        int s1 = g_csr[e + 1];
        float wA = dn * g_dinv[s0];
        float wB = dn * g_dinv[s1];
        float4 v0 = ((const float4*)(feat + (size_t)s0 * D1))[lane];
        float4 v1 = ((const float4*)(feat + (size_t)s1 * D1))[lane];
        acc.x += wA * v0.x + wB * v1.x;
        acc.y += wA * v0.y + wB * v1.y;
        acc.z += wA * v0.z + wB * v1.z;
        acc.w += wA * v0.w + wB * v1.w;
    }
    if (e < end) {
        int s = g_csr[e];
        float w = dn * g_dinv[s];
        float4 v = ((const float4*)(feat + (size_t)s * D1))[lane];
        acc.x += w * v.x; acc.y += w * v.y; acc.z += w * v.z; acc.w += w * v.w;
    }

    if (BIAS) {
        float4 b = *(const float4*)(bias + lane * 4);
        acc.x += b.x; acc.y += b.y; acc.z += b.z; acc.w += b.w;
    }
    if (RELU) {
        acc.x = fmaxf(acc.x, 0.f); acc.y = fmaxf(acc.y, 0.f);
        acc.z = fmaxf(acc.z, 0.f); acc.w = fmaxf(acc.w, 0.f);
    }
    if (CVT) {
        acc.x = f2tf32(acc.x); acc.y = f2tf32(acc.y);
        acc.z = f2tf32(acc.z); acc.w = f2tf32(acc.w);
    }
    ((float4*)(out + (size_t)n * D1))[lane] = acc;
}

// ---------------------------------------------------------------
// TF32 tensor-core GEMM, 2-stage cp.async pipeline, dynamic smem.
// CTA tile 128x128, BK=32, 256 threads (8 warps), warp tile 32x64.
// Inputs are pre-rounded to tf32; smem fill is a raw cp.async copy.
// CVT_OUT rounds the f32 result to tf32 (when C feeds the next GEMM).
// ---------------------------------------------------------------
__device__ __forceinline__ void mma_tf32(float* d, const unsigned* a, const unsigned* b) {
    asm volatile(
        "mma.sync.aligned.m16n8k8.row.col.f32.tf32.tf32.f32 "
        "{%0,%1,%2,%3}, {%4,%5,%6,%7}, {%8,%9}, {%0,%1,%2,%3};"
        : "+f"(d[0]), "+f"(d[1]), "+f"(d[2]), "+f"(d[3])
        : "r"(a[0]), "r"(a[1]), "r"(a[2]), "r"(a[3]), "r"(b[0]), "r"(b[1]));
}

#define GBM 128
#define GBN 128
#define GBK 32
#define APAD 36                         // pad kills stride-32 conflicts
#define BPAD 132
#define A_STAGE (GBM * APAD)            // 4608 floats per stage
#define B_STAGE (GBK * BPAD)            // 4224 floats per stage
#define GEMM_SMEM_FLOATS (2 * A_STAGE + 2 * B_STAGE)   // 17664 floats
#define GEMM_SMEM_BYTES  (GEMM_SMEM_FLOATS * 4)        // 70656 bytes

template<bool RELU, bool BIAS, bool CVT_OUT>
__global__ __launch_bounds__(256)
void gemm_tf32(const float* __restrict__ A, const float* __restrict__ B,
               const float* __restrict__ bias, float* __restrict__ C,
               int M, int N, int K)
{
    extern __shared__ float smem[];
    float* As[2] = { smem,                smem + A_STAGE };
    float* Bs[2] = { smem + 2 * A_STAGE,  smem + 2 * A_STAGE + B_STAGE };

    const int tid  = threadIdx.x;
    const int lane = tid & 31;
    const int wid  = tid >> 5;
    const int wr   = wid >> 1;     // warp row 0..3 (32 M-rows each)
    const int wc   = wid & 1;      // warp col 0..1 (64 N-cols each)
    const int bm   = blockIdx.y * GBM;
    const int bn   = blockIdx.x * GBN;

    float acc[2][8][4];
    #pragma unroll
    for (int i = 0; i < 2; i++)
        #pragma unroll
        for (int j = 0; j < 8; j++)
            #pragma unroll
            for (int q = 0; q < 4; q++) acc[i][j][q] = 0.f;

    // load mappings
    const int a_r = tid >> 3;          // + p*32
    const int a_c = (tid & 7) * 4;
    const int b_r = tid >> 5;          // + p*8
    const int b_c = (tid & 31) * 4;

    auto load_tile = [&](int k0, int st) {
        #pragma unroll
        for (int p = 0; p < 4; p++) {
            int r = a_r + p * 32;
            int am = bm + r;
            uint32_t dstA = (uint32_t)__cvta_generic_to_shared(&As[st][r * APAD + a_c]);
            cp_async16(dstA, A + (size_t)am * K + k0 + a_c, (am < M) ? 16 : 0);
        }
        #pragma unroll
        for (int p = 0; p < 4; p++) {
            int r = b_r + p * 8;
            uint32_t dstB = (uint32_t)__cvta_generic_to_shared(&Bs[st][r * BPAD + b_c]);
            cp_async16(dstB, B + (size_t)(k0 + r) * N + bn + b_c, 16);
        }
    };

    const int ntile = K / GBK;
    load_tile(0, 0);
    asm volatile("cp.async.commit_group;");

    for (int t = 0; t < ntile; t++) {
        if (t + 1 < ntile) {
            load_tile((t + 1) * GBK, (t + 1) & 1);
            asm volatile("cp.async.commit_group;");
            asm volatile("cp.async.wait_group 1;");
        } else {
            asm volatile("cp.async.wait_group 0;");
        }
        __syncthreads();

        const float* Ast = As[t & 1];
        const float* Bst = Bs[t & 1];
        const int g  = lane >> 2;
        const int t4 = lane & 3;
        #pragma unroll
        for (int kk = 0; kk < GBK; kk += 8) {
            unsigned a[2][4];
            #pragma unroll
            for (int mt = 0; mt < 2; mt++) {
                int rb = wr * 32 + mt * 16 + g;
                a[mt][0] = __float_as_uint(Ast[(rb    ) * APAD + kk + t4    ]);
                a[mt][1] = __float_as_uint(Ast[(rb + 8) * APAD + kk + t4    ]);
                a[mt][2] = __float_as_uint(Ast[(rb    ) * APAD + kk + t4 + 4]);
                a[mt][3] = __float_as_uint(Ast[(rb + 8) * APAD + kk + t4 + 4]);
            }
            unsigned b[8][2];
            #pragma unroll
            for (int nt = 0; nt < 8; nt++) {
                int nb = wc * 64 + nt * 8 + g;
                b[nt][0] = __float_as_uint(Bst[(kk + t4    ) * BPAD + nb]);
                b[nt][1] = __float_as_uint(Bst[(kk + t4 + 4) * BPAD + nb]);
            }
            #pragma unroll
            for (int mt = 0; mt < 2; mt++)
                #pragma unroll
                for (int nt = 0; nt < 8; nt++)
                    mma_tf32(acc[mt][nt], a[mt], b[nt]);
        }
        __syncthreads();
    }

    // epilogue
    const int g  = lane >> 2;
    const int t4 = lane & 3;
    #pragma unroll
    for (int mt = 0; mt < 2; mt++) {
        #pragma unroll
        for (int nt = 0; nt < 8; nt++) {
            int col = bn + wc * 64 + nt * 8 + 2 * t4;
            float bx = 0.f, by = 0.f;
            if (BIAS) { bx = bias[col]; by = bias[col + 1]; }
            int r0 = bm + wr * 32 + mt * 16 + g;
            if (r0 < M) {
                float2 v;
                v.x = acc[mt][nt][0] + bx;
                v.y = acc[mt][nt][1] + by;
                if (RELU) { v.x = fmaxf(v.x, 0.f); v.y = fmaxf(v.y, 0.f); }
                if (CVT_OUT) { v.x = f2tf32(v.x); v.y = f2tf32(v.y); }
                *(float2*)(C + (size_t)r0 * N + col) = v;
            }
            int r1 = r0 + 8;
            if (r1 < M) {
                float2 v;
                v.x = acc[mt][nt][2] + bx;
                v.y = acc[mt][nt][3] + by;
                if (RELU) { v.x = fmaxf(v.x, 0.f); v.y = fmaxf(v.y, 0.f); }
                if (CVT_OUT) { v.x = f2tf32(v.x); v.y = f2tf32(v.y); }
                *(float2*)(C + (size_t)r1 * N + col) = v;
            }
        }
    }
}

// ---------------------------------------------------------------
// launch
// ---------------------------------------------------------------
extern "C" void kernel_launch(void* const* d_in, const int* in_sizes, int n_in,
                              void* d_out, int out_size)
{
    const float* x   = (const float*)d_in[0];
    const int*   ei  = (const int*)d_in[1];      // int32 (JAX x64 disabled)
    const float* W1  = (const float*)d_in[2];
    const float* b1  = (const float*)d_in[3];
    const float* W2  = (const float*)d_in[4];
    const float* b2  = (const float*)d_in[5];
    float*       out = (float*)d_out;

    const int E = in_sizes[1] / 2;
    const int* srcIdx = ei;
    const int* dstIdx = ei + E;

    float* bufA = nullptr;  cudaGetSymbolAddress((void**)&bufA, g_bufA);
    float* bufB = nullptr;  cudaGetSymbolAddress((void**)&bufB, g_bufB);
    float* W1t  = nullptr;  cudaGetSymbolAddress((void**)&W1t, g_W1t);
    float* W2t  = nullptr;  cudaGetSymbolAddress((void**)&W2t, g_W2t);

    // raise dynamic smem cap for the GEMM kernels (host attribute set; not a
    // stream op, graph-capture-safe, idempotent)
    cudaFuncSetAttribute(gemm_tf32<true, true, true>,
                         cudaFuncAttributeMaxDynamicSharedMemorySize, GEMM_SMEM_BYTES);
    cudaFuncSetAttribute(gemm_tf32<false, false, false>,
                         cudaFuncAttributeMaxDynamicSharedMemorySize, GEMM_SMEM_BYTES);

    const int T = 256;

    // 0) weight pre-round (tiny)
    k_cvt<<<(D1 * D2 + T - 1) / T, T>>>(W1, W1t, D1 * D2);
    k_cvt<<<(D2 * D1 + T - 1) / T, T>>>(W2, W2t, D2 * D1);

    // 1) degree + dinv + CSR build
    k_zero_cnt<<<(NN + T - 1) / T, T>>>();
    k_deg_count<<<(E + T - 1) / T, T>>>(dstIdx, E);
    k_dinv<<<(NN + T - 1) / T, T>>>();
    k_scan1<<<NCHUNK, 1024>>>();
    k_scan2<<<1, 32>>>();
    k_scan3<<<(NN + T - 1) / T, T>>>();
    k_place<<<(E + T - 1) / T, T>>>(srcIdx, dstIdx, E);

    // 2) layer-1 aggregation (gather, tf32-rounded out): bufA = A_norm @ x
    const int gthreads = NN * 32;
    k_gather<false, false, true><<<(gthreads + T - 1) / T, T>>>(x, bufA, nullptr);

    // 3) out1 = relu(bufA @ W1 + b1) -> bufB [N, 256] (tf32-rounded)
    {
        dim3 grid(D2 / 128, (NN + 127) / 128);
        gemm_tf32<true, true, true><<<grid, 256, GEMM_SMEM_BYTES>>>(bufA, W1t, b1, bufB, NN, D2, D1);
    }

    // 4) h2 = bufB @ W2 -> bufA [N, 128] (full f32)
    {
        dim3 grid(D1 / 128, (NN + 127) / 128);
        gemm_tf32<false, false, false><<<grid, 256, GEMM_SMEM_BYTES>>>(bufB, W2t, nullptr, bufA, NN, D1, D2);
    }

    // 5) layer-2 aggregation (gather) + bias + relu -> out
    k_gather<true, true, false><<<(gthreads + T - 1) / T, T>>>(bufA, out, b2);
}